// round 12
// baseline (speedup 1.0000x reference)
#include <cuda_runtime.h>
#include <cstdint>

#define D 256
#define MAXN 20000
#define MAXE 320000
#define MAXB 64

typedef unsigned long long ull;

// ---------------- scratch (static device allocations; no cudaMalloc) ----------
// h / hnv hold N node rows followed by B state rows (unified GEMM batch).
__device__ __align__(16) float g_h[(MAXN + MAXB) * D];
__device__ __align__(16) float g_hnv[(MAXN + MAXB) * D];
__device__ __align__(16) float g_Wc[2 * D * D];   // fused [512,256] weight
__device__ int   g_deg[MAXN];
__device__ int   g_rowstart[MAXN + 1];
__device__ int   g_cursor[MAXN];
__device__ int   g_csrc[MAXE];
__device__ __align__(16) float g_cw[MAXE];
__device__ int   g_bcnt[MAXB];
__device__ int   g_brow[MAXB + 1];
__device__ int   g_bcur[MAXB];
__device__ int   g_bnodes[MAXN];

// ---------------- packed f32x2 helpers ----------------
__device__ __forceinline__ ull pack2(float x, float y) {
    ull r; asm("mov.b64 %0, {%1, %2};" : "=l"(r) : "f"(x), "f"(y)); return r;
}
__device__ __forceinline__ ull ffma2(ull a, ull b, ull c) {
    ull d; asm("fma.rn.f32x2 %0, %1, %2, %3;" : "=l"(d) : "l"(a), "l"(b), "l"(c));
    return d;
}
__device__ __forceinline__ float lo2(ull x) { return __uint_as_float((unsigned int)x); }
__device__ __forceinline__ float hi2(ull x) { return __uint_as_float((unsigned int)(x >> 32)); }

__device__ __forceinline__ void cp_async16(unsigned int smem_addr, const void* gptr) {
    asm volatile("cp.async.cg.shared.global [%0], [%1], 16;"
                 :: "r"(smem_addr), "l"(gptr));
}

// ---------------- block reduction helper ----------------
__device__ __forceinline__ float block_sum_bcast(float v) {
    __shared__ float red[33];
    int lane = threadIdx.x & 31, w = threadIdx.x >> 5;
#pragma unroll
    for (int o = 16; o; o >>= 1) v += __shfl_down_sync(0xffffffffu, v, o);
    __syncthreads();
    if (lane == 0) red[w] = v;
    __syncthreads();
    if (threadIdx.x == 0) {
        float s = 0.f;
        int nw = (blockDim.x + 31) >> 5;
        for (int i = 0; i < nw; i++) s += red[i];
        red[32] = s;
    }
    __syncthreads();
    return red[32];
}

// ---------------- weight fusion: Wc = [W2@linW_top ; W3@linW_bot] -------------
__global__ void k_fuse(const float* __restrict__ W2, const float* __restrict__ W3,
                       const float* __restrict__ linW) {
    int k0 = blockIdx.x * 8;      // 64 blocks cover 512 rows
    int j = threadIdx.x;          // 256 threads = output column
    __shared__ float sW[8][D];
    const float* wsrc;
    const float* lsrc;
    if (k0 < D) { wsrc = W2 + (size_t)k0 * D;        lsrc = linW; }
    else        { wsrc = W3 + (size_t)(k0 - D) * D;  lsrc = linW + (size_t)D * D; }
#pragma unroll
    for (int r = 0; r < 8; r++) sW[r][j] = wsrc[r * D + j];
    __syncthreads();
    float acc[8];
#pragma unroll
    for (int r = 0; r < 8; r++) acc[r] = 0.f;
    for (int t = 0; t < D; t++) {
        float lv = lsrc[(size_t)t * D + j];
#pragma unroll
        for (int r = 0; r < 8; r++) acc[r] += sW[r][t] * lv;
    }
#pragma unroll
    for (int r = 0; r < 8; r++) g_Wc[(size_t)(k0 + r) * D + j] = acc[r];
}

// ---------------- encoding: h = l2norm(relu(X @ W1)) for nodes + states -------
__global__ void k_encode(const float* __restrict__ X, const float* __restrict__ Xs,
                         const float* __restrict__ W1, float* __restrict__ h, int N) {
    int i = blockIdx.x;
    int d = threadIdx.x;
    const float* xr = (i < N) ? (X + (size_t)i * 2) : (Xs + (size_t)(i - N) * 2);
    float v = fmaxf(xr[0] * W1[d] + xr[1] * W1[D + d], 0.f);
    float ss = block_sum_bcast(v * v);
    h[(size_t)i * D + d] = v / fmaxf(sqrtf(ss), 1e-12f);
}

// ---------------- CSR build ----------------
__global__ void k_zero(int N, int B) {
    int i = blockIdx.x * blockDim.x + threadIdx.x;
    if (i < N) { g_deg[i] = 0; g_cursor[i] = 0; }
    if (i < B) { g_bcnt[i] = 0; g_bcur[i] = 0; }
}

__global__ void k_hist(const int* __restrict__ dst, const int* __restrict__ batch,
                       int E, int N) {
    int i = blockIdx.x * blockDim.x + threadIdx.x;
    if (i < E) atomicAdd(&g_deg[dst[i]], 1);
    if (i < N) atomicAdd(&g_bcnt[batch[i]], 1);
}

// exclusive scans: block 0 -> (deg,rowstart,N), block 1 -> (bcnt,brow,B)
__global__ void k_scan2(int N, int B) {
    const int* cnt; int* out; int n;
    if (blockIdx.x == 0) { cnt = g_deg;  out = g_rowstart; n = N; }
    else                 { cnt = g_bcnt; out = g_brow;     n = B; }
    __shared__ int s[1024];
    const int T = 1024;
    int t = threadIdx.x;
    int chunk = (n + T - 1) / T;
    int base = t * chunk;
    int run = 0;
    for (int c = 0; c < chunk; c++) { int i = base + c; if (i < n) run += cnt[i]; }
    s[t] = run;
    __syncthreads();
    for (int off = 1; off < T; off <<= 1) {
        int v = (t >= off) ? s[t - off] : 0;
        __syncthreads();
        s[t] += v;
        __syncthreads();
    }
    run = (t > 0) ? s[t - 1] : 0;
    for (int c = 0; c < chunk; c++) {
        int i = base + c;
        if (i < n) { out[i] = run; run += cnt[i]; }
    }
    if (t == T - 1) out[n] = s[T - 1];
}

__global__ void k_scatter(const int* __restrict__ src, const int* __restrict__ dst,
                          const float* __restrict__ w, const int* __restrict__ batch,
                          int E, int N) {
    int i = blockIdx.x * blockDim.x + threadIdx.x;
    if (i < E) {
        int dd = dst[i];
        int pos = g_rowstart[dd] + atomicAdd(&g_cursor[dd], 1);
        g_csrc[pos] = src[i];
        g_cw[pos] = w[i];
    }
    if (i < N) {
        int b = batch[i];
        int pos = g_brow[b] + atomicAdd(&g_bcur[b], 1);
        g_bnodes[pos] = i;
    }
}

// ---------------- merged aggregation (vectorized, 64 threads/block) -----------
__global__ void k_gather4(const float* __restrict__ h, float* __restrict__ hnv, int N) {
    int blk = blockIdx.x;
    int c4 = threadIdx.x << 2;         // column offset 0,4,...,252
    float4 acc = make_float4(0.f, 0.f, 0.f, 0.f);
    if (blk < N) {
        int s = g_rowstart[blk], e = g_rowstart[blk + 1];
        int j = s;
        for (; j + 2 <= e; j += 2) {
            int   s0 = g_csrc[j],     s1 = g_csrc[j + 1];
            float w0 = g_cw[j],       w1 = g_cw[j + 1];
            float4 v0 = *reinterpret_cast<const float4*>(&h[(size_t)s0 * D + c4]);
            float4 v1 = *reinterpret_cast<const float4*>(&h[(size_t)s1 * D + c4]);
            acc.x += w0 * v0.x + w1 * v1.x;
            acc.y += w0 * v0.y + w1 * v1.y;
            acc.z += w0 * v0.z + w1 * v1.z;
            acc.w += w0 * v0.w + w1 * v1.w;
        }
        if (j < e) {
            int   s0 = g_csrc[j];
            float w0 = g_cw[j];
            float4 v0 = *reinterpret_cast<const float4*>(&h[(size_t)s0 * D + c4]);
            acc.x += w0 * v0.x; acc.y += w0 * v0.y;
            acc.z += w0 * v0.z; acc.w += w0 * v0.w;
        }
    } else {
        int b = blk - N;
        int s = g_brow[b], e = g_brow[b + 1];
        int j = s;
        for (; j + 2 <= e; j += 2) {
            int s0 = g_bnodes[j], s1 = g_bnodes[j + 1];
            float4 v0 = *reinterpret_cast<const float4*>(&h[(size_t)s0 * D + c4]);
            float4 v1 = *reinterpret_cast<const float4*>(&h[(size_t)s1 * D + c4]);
            acc.x += v0.x + v1.x; acc.y += v0.y + v1.y;
            acc.z += v0.z + v1.z; acc.w += v0.w + v1.w;
        }
        if (j < e) {
            int s0 = g_bnodes[j];
            float4 v0 = *reinterpret_cast<const float4*>(&h[(size_t)s0 * D + c4]);
            acc.x += v0.x; acc.y += v0.y; acc.z += v0.z; acc.w += v0.w;
        }
    }
    *reinterpret_cast<float4*>(&hnv[(size_t)blk * D + c4]) = acc;
}

// ---------------- fused GEMM + bias + relu + L2 normalize (in place) ----------
// out[M,256] = l2norm_rows(relu([in0 | in1] @ Wc + bias))
// BM=64, BN=256, BK=16, 256 threads, 8x8 per thread (row-paired f32x2).
// Software-pipelined: double-buffered smem; B via cp.async.cg (no reg staging),
// A prefetched 2 tiles ahead through 4 registers then transposed-STS.
// PROVEN thread mapping (R3/R6/R10); do NOT retile or cap regs below 128
// (R5/R9 spilled inside the FFMA2 loop).
__global__ void __launch_bounds__(256, 2) k_gemm_norm(
    const float* __restrict__ in0, const float* __restrict__ in1,
    const float* __restrict__ bias, float* __restrict__ outp, int M) {
    const int BM = 64, BK = 16, NT = (2 * D) / BK;  // 32 tiles
    __shared__ float As[2][BK][BM];    // transposed: As[buf][k][m]
    __shared__ float Bs[2][BK][D];
    int row0 = blockIdx.x * BM;
    int tid = threadIdx.x;
    int tx = tid & 31;   // 8 cols: {tx*4..+3} and {128+tx*4..+3}
    int ty = tid >> 5;   // rows ty*8..ty*8+7 (whole warp shares ty)

    // A-tile coords: one float4 per thread
    int arow = tid >> 2;            // 0..63
    int k4 = (tid & 3) << 2;        // 0,4,8,12
    int grow = row0 + arow;

    ull acc[4][8];       // [row-pair][col], rows (ty*8+2mp, ty*8+2mp+1)
#pragma unroll
    for (int mp = 0; mp < 4; mp++)
#pragma unroll
        for (int n = 0; n < 8; n++) acc[mp][n] = 0ull;

    // lambdas -------------------------------------------------------------
    auto ldA = [&](int t) -> float4 {
        int gk = t * BK + k4;                    // tile entirely in in0 or in1
        const float* src = (gk < D) ? (in0 + (size_t)grow * D + gk)
                                    : (in1 + (size_t)grow * D + (gk - D));
        return (grow < M) ? *reinterpret_cast<const float4*>(src)
                          : make_float4(0.f, 0.f, 0.f, 0.f);
    };
    auto stA = [&](int buf, float4 v) {
        As[buf][k4 + 0][arow] = v.x;
        As[buf][k4 + 1][arow] = v.y;
        As[buf][k4 + 2][arow] = v.z;
        As[buf][k4 + 3][arow] = v.w;
    };
    auto cpB = [&](int t, int buf) {
#pragma unroll
        for (int i = 0; i < 4; i++) {
            int v = tid + i * 256;               // 0..1023
            int brow = v >> 6;                   // 0..15
            int bc = (v & 63) << 2;              // 0..252
            cp_async16((unsigned int)__cvta_generic_to_shared(&Bs[buf][brow][bc]),
                       &g_Wc[(size_t)(t * BK + brow) * D + bc]);
        }
        asm volatile("cp.async.commit_group;");
    };

    // prologue: tile 0 staged, tile 1's A in flight
    float4 aR = ldA(0);
    cpB(0, 0);
    stA(0, aR);
    aR = ldA(1);

    for (int t = 0; t < NT; t++) {
        int cur = t & 1;
        if (t + 1 < NT) {                    // stage tile t+1 into the idle buffer
            stA(cur ^ 1, aR);
            cpB(t + 1, cur ^ 1);
        }
        if (t + 2 < NT) aR = ldA(t + 2);     // long-latency prefetch
        if (t + 1 < NT) asm volatile("cp.async.wait_group 1;");
        else            asm volatile("cp.async.wait_group 0;");
        __syncthreads();                     // As/Bs[cur] visible to all

#pragma unroll
        for (int k = 0; k < BK; k++) {
            const ull* ap = reinterpret_cast<const ull*>(&As[cur][k][ty * 8]);  // broadcast
            ull a2[4];
            a2[0] = ap[0]; a2[1] = ap[1]; a2[2] = ap[2]; a2[3] = ap[3];
            float4 b0 = *reinterpret_cast<const float4*>(&Bs[cur][k][tx * 4]);
            float4 b1 = *reinterpret_cast<const float4*>(&Bs[cur][k][128 + tx * 4]);
            ull bn2[8];
            bn2[0] = pack2(b0.x, b0.x); bn2[1] = pack2(b0.y, b0.y);
            bn2[2] = pack2(b0.z, b0.z); bn2[3] = pack2(b0.w, b0.w);
            bn2[4] = pack2(b1.x, b1.x); bn2[5] = pack2(b1.y, b1.y);
            bn2[6] = pack2(b1.z, b1.z); bn2[7] = pack2(b1.w, b1.w);
#pragma unroll
            for (int mp = 0; mp < 4; mp++)
#pragma unroll
                for (int n = 0; n < 8; n++)
                    acc[mp][n] = ffma2(a2[mp], bn2[n], acc[mp][n]);
        }
        __syncthreads();                     // buffer free for overwrite
    }

    // epilogue: bias + relu + per-row L2 normalize (warp covers full row)
    float4 bv0 = *reinterpret_cast<const float4*>(&bias[tx * 4]);
    float4 bv1 = *reinterpret_cast<const float4*>(&bias[128 + tx * 4]);
    float bias_v[8] = {bv0.x, bv0.y, bv0.z, bv0.w, bv1.x, bv1.y, bv1.z, bv1.w};
#pragma unroll
    for (int m = 0; m < 8; m++) {
        int mp = m >> 1;
        bool hipart = (m & 1);
        float v[8];
#pragma unroll
        for (int n = 0; n < 8; n++) {
            float a = hipart ? hi2(acc[mp][n]) : lo2(acc[mp][n]);
            v[n] = fmaxf(a + bias_v[n], 0.f);
        }
        float ssq = 0.f;
#pragma unroll
        for (int n = 0; n < 8; n++) ssq += v[n] * v[n];
#pragma unroll
        for (int o = 16; o; o >>= 1) ssq += __shfl_xor_sync(0xffffffffu, ssq, o);
        float s = 1.f / fmaxf(sqrtf(ssq), 1e-12f);
        int gr = row0 + ty * 8 + m;
        if (gr < M) {
            float4 o0 = make_float4(v[0] * s, v[1] * s, v[2] * s, v[3] * s);
            float4 o1 = make_float4(v[4] * s, v[5] * s, v[6] * s, v[7] * s);
            *reinterpret_cast<float4*>(&outp[(size_t)gr * D + tx * 4]) = o0;
            *reinterpret_cast<float4*>(&outp[(size_t)gr * D + 128 + tx * 4]) = o1;
        }
    }
}

// ---------------- decode ----------------
__global__ void k_decode(const float* __restrict__ h, const float* __restrict__ hs,
                         const int* __restrict__ action_idx,
                         const float* __restrict__ W4, const float* __restrict__ W5,
                         float* __restrict__ out) {
    int b = blockIdx.x;
    int d = threadIdx.x;
    float s = block_sum_bcast(hs[(size_t)b * D + d] * W4[d]);
    int a = action_idx[b];
    float q = fmaxf(h[(size_t)a * D + d] * s, 0.f) * W5[d];
    float Q = block_sum_bcast(q);
    if (d == 0) out[b] = Q;
}

// ---------------- launcher ----------------
extern "C" void kernel_launch(void* const* d_in, const int* in_sizes, int n_in,
                              void* d_out, int out_size) {
    const int*   edge_src     = (const int*)d_in[0];
    const int*   edge_dst     = (const int*)d_in[1];
    const float* edge_w       = (const float*)d_in[2];
    const int*   batch_assign = (const int*)d_in[3];
    const int*   action_idx   = (const int*)d_in[4];
    const float* X            = (const float*)d_in[5];
    const float* Xs           = (const float*)d_in[6];
    const float* W1           = (const float*)d_in[7];
    const float* W2           = (const float*)d_in[8];
    const float* W3           = (const float*)d_in[9];
    const float* linW         = (const float*)d_in[10];
    const float* linb         = (const float*)d_in[11];
    const float* W4           = (const float*)d_in[12];
    const float* W5           = (const float*)d_in[13];
    float* out = (float*)d_out;

    int E = in_sizes[0];
    int N = in_sizes[3];
    int B = in_sizes[4];
    int M = N + B;   // unified row count: N node rows + B state rows

    float *p_h, *p_hnv;
    cudaGetSymbolAddress((void**)&p_h, g_h);
    cudaGetSymbolAddress((void**)&p_hnv, g_hnv);

    // fused weights + encoding (state rows appended at h[N..N+B))
    k_fuse<<<64, 256>>>(W2, W3, linW);
    k_encode<<<M, 256>>>(X, Xs, W1, p_h, N);

    // CSR build (edges by dst, nodes by batch) — merged launches
    k_zero<<<(N + 255) / 256, 256>>>(N, B);
    k_hist<<<(E + 255) / 256, 256>>>(edge_dst, batch_assign, E, N);
    k_scan2<<<2, 1024>>>(N, B);
    k_scatter<<<(E + 255) / 256, 256>>>(edge_src, edge_dst, edge_w, batch_assign, E, N);

    // 3 message-passing depths: gather then fused GEMM+normalize (in place)
    int gblocks = (M + 63) / 64;
    for (int it = 0; it < 3; it++) {
        k_gather4<<<M, 64>>>(p_h, p_hnv, N);
        k_gemm_norm<<<gblocks, 256>>>(p_h, p_hnv, linb, p_h, M);
    }

    // decode
    k_decode<<<B, 256>>>(p_h, p_h + (size_t)N * D, action_idx, W4, W5, out);
}

// round 14
// speedup vs baseline: 1.2143x; 1.2143x over previous
#include <cuda_runtime.h>
#include <cuda_bf16.h>
#include <mma.h>
#include <cstdint>

using namespace nvcuda;

#define D 256
#define MAXN 20000
#define MAXE 320000
#define MAXB 64

typedef unsigned long long ull;

// ---------------- scratch (static device allocations; no cudaMalloc) ----------
__device__ __align__(16) float g_h[(MAXN + MAXB) * D];
__device__ __align__(16) float g_hnv[(MAXN + MAXB) * D];
__device__ __align__(16) float g_htmp[(MAXN + MAXB) * D];
__device__ __align__(16) float g_Wc[2 * D * D];   // fused [512,256] fp32 weight
// Row-major bf16 split images of Wc: [512][256]
__device__ __align__(16) __nv_bfloat16 g_Wh[2 * D * D];
__device__ __align__(16) __nv_bfloat16 g_Wl[2 * D * D];
__device__ int   g_deg[MAXN];
__device__ int   g_rowstart[MAXN + 1];
__device__ int   g_cursor[MAXN];
__device__ int   g_csrc[MAXE];
__device__ __align__(16) float g_cw[MAXE];
__device__ int   g_bcnt[MAXB];
__device__ int   g_brow[MAXB + 1];
__device__ int   g_bcur[MAXB];
__device__ int   g_bnodes[MAXN];

// ---------------- block reduction helper ----------------
__device__ __forceinline__ float block_sum_bcast(float v) {
    __shared__ float red[33];
    int lane = threadIdx.x & 31, w = threadIdx.x >> 5;
#pragma unroll
    for (int o = 16; o; o >>= 1) v += __shfl_down_sync(0xffffffffu, v, o);
    __syncthreads();
    if (lane == 0) red[w] = v;
    __syncthreads();
    if (threadIdx.x == 0) {
        float s = 0.f;
        int nw = (blockDim.x + 31) >> 5;
        for (int i = 0; i < nw; i++) s += red[i];
        red[32] = s;
    }
    __syncthreads();
    return red[32];
}

// ---------------- weight fusion: Wc = [W2@linW_top ; W3@linW_bot] -------------
__global__ void k_fuse(const float* __restrict__ W2, const float* __restrict__ W3,
                       const float* __restrict__ linW) {
    int k0 = blockIdx.x * 8;
    int j = threadIdx.x;
    __shared__ float sW[8][D];
    const float* wsrc;
    const float* lsrc;
    if (k0 < D) { wsrc = W2 + (size_t)k0 * D;        lsrc = linW; }
    else        { wsrc = W3 + (size_t)(k0 - D) * D;  lsrc = linW + (size_t)D * D; }
#pragma unroll
    for (int r = 0; r < 8; r++) sW[r][j] = wsrc[r * D + j];
    __syncthreads();
    float acc[8];
#pragma unroll
    for (int r = 0; r < 8; r++) acc[r] = 0.f;
    for (int t = 0; t < D; t++) {
        float lv = lsrc[(size_t)t * D + j];
#pragma unroll
        for (int r = 0; r < 8; r++) acc[r] += sW[r][t] * lv;
    }
#pragma unroll
    for (int r = 0; r < 8; r++) g_Wc[(size_t)(k0 + r) * D + j] = acc[r];
}

// ---------------- weight split: Wc -> row-major bf16 hi/lo --------------------
__global__ void k_wsplit() {
    int i = blockIdx.x * blockDim.x + threadIdx.x;   // 512 blocks x 256 = 131072
    float val = g_Wc[i];
    __nv_bfloat16 hi = __float2bfloat16(val);
    __nv_bfloat16 lo = __float2bfloat16(val - __bfloat162float(hi));
    g_Wh[i] = hi;
    g_Wl[i] = lo;
}

// ---------------- encoding: h = l2norm(relu(X @ W1)) for nodes + states -------
__global__ void k_encode(const float* __restrict__ X, const float* __restrict__ Xs,
                         const float* __restrict__ W1, float* __restrict__ h, int N) {
    int i = blockIdx.x;
    int d = threadIdx.x;
    const float* xr = (i < N) ? (X + (size_t)i * 2) : (Xs + (size_t)(i - N) * 2);
    float v = fmaxf(xr[0] * W1[d] + xr[1] * W1[D + d], 0.f);
    float ss = block_sum_bcast(v * v);
    h[(size_t)i * D + d] = v / fmaxf(sqrtf(ss), 1e-12f);
}

// ---------------- CSR build ----------------
__global__ void k_zero(int N, int B) {
    int i = blockIdx.x * blockDim.x + threadIdx.x;
    if (i < N) { g_deg[i] = 0; g_cursor[i] = 0; }
    if (i < B) { g_bcnt[i] = 0; g_bcur[i] = 0; }
}

__global__ void k_hist(const int* __restrict__ dst, const int* __restrict__ batch,
                       int E, int N) {
    int i = blockIdx.x * blockDim.x + threadIdx.x;
    if (i < E) atomicAdd(&g_deg[dst[i]], 1);
    if (i < N) atomicAdd(&g_bcnt[batch[i]], 1);
}

__global__ void k_scan2(int N, int B) {
    const int* cnt; int* out; int n;
    if (blockIdx.x == 0) { cnt = g_deg;  out = g_rowstart; n = N; }
    else                 { cnt = g_bcnt; out = g_brow;     n = B; }
    __shared__ int s[1024];
    const int T = 1024;
    int t = threadIdx.x;
    int chunk = (n + T - 1) / T;
    int base = t * chunk;
    int run = 0;
    for (int c = 0; c < chunk; c++) { int i = base + c; if (i < n) run += cnt[i]; }
    s[t] = run;
    __syncthreads();
    for (int off = 1; off < T; off <<= 1) {
        int v = (t >= off) ? s[t - off] : 0;
        __syncthreads();
        s[t] += v;
        __syncthreads();
    }
    run = (t > 0) ? s[t - 1] : 0;
    for (int c = 0; c < chunk; c++) {
        int i = base + c;
        if (i < n) { out[i] = run; run += cnt[i]; }
    }
    if (t == T - 1) out[n] = s[T - 1];
}

__global__ void k_scatter(const int* __restrict__ src, const int* __restrict__ dst,
                          const float* __restrict__ w, const int* __restrict__ batch,
                          int E, int N) {
    int i = blockIdx.x * blockDim.x + threadIdx.x;
    if (i < E) {
        int dd = dst[i];
        int pos = g_rowstart[dd] + atomicAdd(&g_cursor[dd], 1);
        g_csrc[pos] = src[i];
        g_cw[pos] = w[i];
    }
    if (i < N) {
        int b = batch[i];
        int pos = g_brow[b] + atomicAdd(&g_bcur[b], 1);
        g_bnodes[pos] = i;
    }
}

// ---------------- merged aggregation (vectorized, 64 threads/block) -----------
__global__ void k_gather4(const float* __restrict__ h, float* __restrict__ hnv, int N) {
    int blk = blockIdx.x;
    int c4 = threadIdx.x << 2;
    float4 acc = make_float4(0.f, 0.f, 0.f, 0.f);
    if (blk < N) {
        int s = g_rowstart[blk], e = g_rowstart[blk + 1];
        int j = s;
        for (; j + 2 <= e; j += 2) {
            int   s0 = g_csrc[j],     s1 = g_csrc[j + 1];
            float w0 = g_cw[j],       w1 = g_cw[j + 1];
            float4 v0 = *reinterpret_cast<const float4*>(&h[(size_t)s0 * D + c4]);
            float4 v1 = *reinterpret_cast<const float4*>(&h[(size_t)s1 * D + c4]);
            acc.x += w0 * v0.x + w1 * v1.x;
            acc.y += w0 * v0.y + w1 * v1.y;
            acc.z += w0 * v0.z + w1 * v1.z;
            acc.w += w0 * v0.w + w1 * v1.w;
        }
        if (j < e) {
            int   s0 = g_csrc[j];
            float w0 = g_cw[j];
            float4 v0 = *reinterpret_cast<const float4*>(&h[(size_t)s0 * D + c4]);
            acc.x += w0 * v0.x; acc.y += w0 * v0.y;
            acc.z += w0 * v0.z; acc.w += w0 * v0.w;
        }
    } else {
        int b = blk - N;
        int s = g_brow[b], e = g_brow[b + 1];
        int j = s;
        for (; j + 2 <= e; j += 2) {
            int s0 = g_bnodes[j], s1 = g_bnodes[j + 1];
            float4 v0 = *reinterpret_cast<const float4*>(&h[(size_t)s0 * D + c4]);
            float4 v1 = *reinterpret_cast<const float4*>(&h[(size_t)s1 * D + c4]);
            acc.x += v0.x + v1.x; acc.y += v0.y + v1.y;
            acc.z += v0.z + v1.z; acc.w += v0.w + v1.w;
        }
        if (j < e) {
            int s0 = g_bnodes[j];
            float4 v0 = *reinterpret_cast<const float4*>(&h[(size_t)s0 * D + c4]);
            acc.x += v0.x; acc.y += v0.y; acc.z += v0.z; acc.w += v0.w;
        }
    }
    *reinterpret_cast<float4*>(&hnv[(size_t)blk * D + c4]) = acc;
}

// ---------------- wmma GEMM: out = relu([in0 | in1] @ Wc + bias) --------------
// Split-bf16 HMMA: D += Ahi*Bhi + Ahi*Blo + Alo*Bhi (fp32 accumulate).
// BM=64, BN=128, BK=32; 8 warps (2 row x 4 col), warp tile 32x32 = 2x2 frags.
// Output is UNNORMALIZED; k_normalize runs after.
static const int A_LD = 40;     // bf16 elems per A smem row (32 + pad)
static const int B_LD = 136;    // bf16 elems per B smem row (128 + pad)
static const int S_LD = 132;    // float elems per staging row (128 + pad)

__global__ void k_gemm_wmma(
    const float* __restrict__ in0, const float* __restrict__ in1,
    const float* __restrict__ bias, float* __restrict__ outp, int M) {
    // smem union: stage-in (A hi/lo + B hi/lo = 27.6KB) vs epilogue (64x132 f32 = 33.8KB)
    __shared__ __align__(16) char sm[64 * S_LD * 4];
    __nv_bfloat16* Ahi = reinterpret_cast<__nv_bfloat16*>(sm);
    __nv_bfloat16* Alo = Ahi + 64 * A_LD;
    __nv_bfloat16* Bhi = reinterpret_cast<__nv_bfloat16*>(sm + 2 * 64 * A_LD * 2);
    __nv_bfloat16* Blo = Bhi + 32 * B_LD;
    float* stage = reinterpret_cast<float*>(sm);

    int tid = threadIdx.x;
    int wid = tid >> 5;
    int warpRow = wid >> 2;        // 0..1
    int warpCol = wid & 3;         // 0..3
    int row0 = blockIdx.y * 64;
    int col0 = blockIdx.x * 128;

    wmma::fragment<wmma::accumulator, 16, 16, 16, float> acc[2][2];
#pragma unroll
    for (int i = 0; i < 2; i++)
#pragma unroll
        for (int j = 0; j < 2; j++) wmma::fill_fragment(acc[i][j], 0.f);

    for (int t = 0; t < 16; t++) {
        // ---- A tile: 64 rows x 32 k fp32 -> hi/lo bf16 in smem ----
        const float* src = (t < 8) ? in0 : in1;
        int kbase = (t & 7) * 32;
#pragma unroll
        for (int it = 0; it < 2; it++) {
            int id = tid + it * 256;       // 0..511
            int r = id >> 3;               // 0..63
            int c4 = (id & 7) << 2;        // 0..28
            int grow = row0 + r;
            float4 v = make_float4(0.f, 0.f, 0.f, 0.f);
            if (grow < M)
                v = *reinterpret_cast<const float4*>(&src[(size_t)grow * D + kbase + c4]);
            __nv_bfloat16 h0 = __float2bfloat16(v.x), h1 = __float2bfloat16(v.y);
            __nv_bfloat16 h2 = __float2bfloat16(v.z), h3 = __float2bfloat16(v.w);
            __nv_bfloat16 l0 = __float2bfloat16(v.x - __bfloat162float(h0));
            __nv_bfloat16 l1 = __float2bfloat16(v.y - __bfloat162float(h1));
            __nv_bfloat16 l2 = __float2bfloat16(v.z - __bfloat162float(h2));
            __nv_bfloat16 l3 = __float2bfloat16(v.w - __bfloat162float(h3));
            uint2 uh, ul;
            uh.x = (unsigned)__bfloat16_as_ushort(h0) | ((unsigned)__bfloat16_as_ushort(h1) << 16);
            uh.y = (unsigned)__bfloat16_as_ushort(h2) | ((unsigned)__bfloat16_as_ushort(h3) << 16);
            ul.x = (unsigned)__bfloat16_as_ushort(l0) | ((unsigned)__bfloat16_as_ushort(l1) << 16);
            ul.y = (unsigned)__bfloat16_as_ushort(l2) | ((unsigned)__bfloat16_as_ushort(l3) << 16);
            *reinterpret_cast<uint2*>(&Ahi[r * A_LD + c4]) = uh;
            *reinterpret_cast<uint2*>(&Alo[r * A_LD + c4]) = ul;
        }
        // ---- B tile: 32 k x 128 cols bf16 from pre-split images ----
#pragma unroll
        for (int it = 0; it < 2; it++) {
            int id = tid + it * 256;       // 0..511
            int r = id >> 4;               // 0..31
            int c8 = (id & 15) << 3;       // 0..120
            size_t goff = (size_t)(t * 32 + r) * D + col0 + c8;
            *reinterpret_cast<uint4*>(&Bhi[r * B_LD + c8]) =
                *reinterpret_cast<const uint4*>(&g_Wh[goff]);
            *reinterpret_cast<uint4*>(&Blo[r * B_LD + c8]) =
                *reinterpret_cast<const uint4*>(&g_Wl[goff]);
        }
        __syncthreads();

        // ---- compute: 2 k16 sub-steps ----
#pragma unroll
        for (int kk = 0; kk < 32; kk += 16) {
            wmma::fragment<wmma::matrix_a, 16, 16, 16, __nv_bfloat16, wmma::row_major> ah[2], al[2];
            wmma::fragment<wmma::matrix_b, 16, 16, 16, __nv_bfloat16, wmma::row_major> bh[2], bl[2];
#pragma unroll
            for (int i = 0; i < 2; i++) {
                int ar = warpRow * 32 + i * 16;
                wmma::load_matrix_sync(ah[i], &Ahi[ar * A_LD + kk], A_LD);
                wmma::load_matrix_sync(al[i], &Alo[ar * A_LD + kk], A_LD);
            }
#pragma unroll
            for (int j = 0; j < 2; j++) {
                int bc = warpCol * 32 + j * 16;
                wmma::load_matrix_sync(bh[j], &Bhi[kk * B_LD + bc], B_LD);
                wmma::load_matrix_sync(bl[j], &Blo[kk * B_LD + bc], B_LD);
            }
#pragma unroll
            for (int i = 0; i < 2; i++)
#pragma unroll
                for (int j = 0; j < 2; j++) {
                    wmma::mma_sync(acc[i][j], ah[i], bh[j], acc[i][j]);
                    wmma::mma_sync(acc[i][j], ah[i], bl[j], acc[i][j]);
                    wmma::mma_sync(acc[i][j], al[i], bh[j], acc[i][j]);
                }
        }
        __syncthreads();
    }

    // ---- epilogue: stage accum to smem, then bias+relu coalesced STG ----
#pragma unroll
    for (int i = 0; i < 2; i++)
#pragma unroll
        for (int j = 0; j < 2; j++)
            wmma::store_matrix_sync(
                &stage[(warpRow * 32 + i * 16) * S_LD + warpCol * 32 + j * 16],
                acc[i][j], S_LD, wmma::mem_row_major);
    __syncthreads();
#pragma unroll
    for (int it = 0; it < 8; it++) {
        int id = tid + it * 256;           // 0..2047
        int r = id >> 5;                   // 0..63
        int c4 = (id & 31) << 2;           // 0..124
        int gr = row0 + r;
        if (gr < M) {
            float4 o;
            o.x = fmaxf(stage[r * S_LD + c4 + 0] + bias[col0 + c4 + 0], 0.f);
            o.y = fmaxf(stage[r * S_LD + c4 + 1] + bias[col0 + c4 + 1], 0.f);
            o.z = fmaxf(stage[r * S_LD + c4 + 2] + bias[col0 + c4 + 2], 0.f);
            o.w = fmaxf(stage[r * S_LD + c4 + 3] + bias[col0 + c4 + 3], 0.f);
            *reinterpret_cast<float4*>(&outp[(size_t)gr * D + col0 + c4]) = o;
        }
    }
}

// ---------------- row L2 normalize: out = in / ||in||_2 ----------------
__global__ void k_normalize(const float* __restrict__ in, float* __restrict__ out) {
    int i = blockIdx.x;
    int d = threadIdx.x;
    float v = in[(size_t)i * D + d];
    float ss = block_sum_bcast(v * v);
    out[(size_t)i * D + d] = v / fmaxf(sqrtf(ss), 1e-12f);
}

// ---------------- decode ----------------
__global__ void k_decode(const float* __restrict__ h, const float* __restrict__ hs,
                         const int* __restrict__ action_idx,
                         const float* __restrict__ W4, const float* __restrict__ W5,
                         float* __restrict__ out) {
    int b = blockIdx.x;
    int d = threadIdx.x;
    float s = block_sum_bcast(hs[(size_t)b * D + d] * W4[d]);
    int a = action_idx[b];
    float q = fmaxf(h[(size_t)a * D + d] * s, 0.f) * W5[d];
    float Q = block_sum_bcast(q);
    if (d == 0) out[b] = Q;
}

// ---------------- launcher ----------------
extern "C" void kernel_launch(void* const* d_in, const int* in_sizes, int n_in,
                              void* d_out, int out_size) {
    const int*   edge_src     = (const int*)d_in[0];
    const int*   edge_dst     = (const int*)d_in[1];
    const float* edge_w       = (const float*)d_in[2];
    const int*   batch_assign = (const int*)d_in[3];
    const int*   action_idx   = (const int*)d_in[4];
    const float* X            = (const float*)d_in[5];
    const float* Xs           = (const float*)d_in[6];
    const float* W1           = (const float*)d_in[7];
    const float* W2           = (const float*)d_in[8];
    const float* W3           = (const float*)d_in[9];
    const float* linW         = (const float*)d_in[10];
    const float* linb         = (const float*)d_in[11];
    const float* W4           = (const float*)d_in[12];
    const float* W5           = (const float*)d_in[13];
    float* out = (float*)d_out;

    int E = in_sizes[0];
    int N = in_sizes[3];
    int B = in_sizes[4];
    int M = N + B;

    float *p_h, *p_hnv, *p_htmp;
    cudaGetSymbolAddress((void**)&p_h, g_h);
    cudaGetSymbolAddress((void**)&p_hnv, g_hnv);
    cudaGetSymbolAddress((void**)&p_htmp, g_htmp);

    // fused weights + bf16 split + encoding
    k_fuse<<<64, 256>>>(W2, W3, linW);
    k_wsplit<<<512, 256>>>();
    k_encode<<<M, 256>>>(X, Xs, W1, p_h, N);

    // CSR build (edges by dst, nodes by batch)
    k_zero<<<(N + 255) / 256, 256>>>(N, B);
    k_hist<<<(E + 255) / 256, 256>>>(edge_dst, batch_assign, E, N);
    k_scan2<<<2, 1024>>>(N, B);
    k_scatter<<<(E + 255) / 256, 256>>>(edge_src, edge_dst, edge_w, batch_assign, E, N);

    // 3 depths: gather -> wmma GEMM (to htmp, unnormalized) -> normalize
    dim3 ggrid(2, (M + 63) / 64);
    for (int it = 0; it < 3; it++) {
        k_gather4<<<M, 64>>>(p_h, p_hnv, N);
        k_gemm_wmma<<<ggrid, 256>>>(p_h, p_hnv, linb, p_htmp, M);
        k_normalize<<<M, 256>>>(p_htmp, p_h);
    }

    // decode
    k_decode<<<B, 256>>>(p_h, p_h + (size_t)N * D, action_idx, W4, W5, out);
}